// round 6
// baseline (speedup 1.0000x reference)
#include <cuda_runtime.h>
#include <cuda_bf16.h>

// ---------------------------------------------------------------------------
// LGNInputLayerCell: i_in[post] += weights[s] * (inputs_t[pre[s]] > 0)
// inputs (metadata order):
//   d_in[0] : int32  inputs_t   [N_SOURCE]      (17400)
//   d_in[1] : int32  indices    [N_SYN, 2]      (post, pre) interleaved
//   d_in[2] : float  weights    [N_SYN]
//   d_in[3] : int32  n_post     (unused; out_size == n_post)
// output: float [n_post]
// ---------------------------------------------------------------------------

// Active-source bitmask scratch (global, built by prologue).
// 2048 words = 65536 sources capacity (N_SOURCE = 17400 -> 544 words used).
#define MASK_WORDS_MAX 2048
__device__ unsigned int g_active_mask[MASK_WORDS_MAX];

// ---------------------------------------------------------------------------
// Prologue: build the active bitmask (ballot, 1 thread / source) AND zero the
// 0xAA-poisoned output.
// ---------------------------------------------------------------------------
__global__ void prologue_kernel(const int* __restrict__ inputs_t,
                                int n_source,
                                float* __restrict__ out, int n_post) {
    const int i = blockIdx.x * blockDim.x + threadIdx.x;

    // --- bitmask build: whole warps inside/outside (round-up-32 bound) ---
    const int n_src32 = (n_source + 31) & ~31;
    if (i < n_src32) {
        int v = (i < n_source) ? inputs_t[i] : 0;
        unsigned int b = __ballot_sync(0xffffffffu, v > 0);
        if ((threadIdx.x & 31) == 0) g_active_mask[i >> 5] = b;
    }

    // --- zero output, 4 floats per thread ---
    const int base = i << 2;
    if (base + 3 < n_post) {
        *reinterpret_cast<float4*>(out + base) = make_float4(0.f, 0.f, 0.f, 0.f);
    } else if (base < n_post) {
        for (int j = base; j < n_post; ++j) out[j] = 0.0f;
    }
}

// ---------------------------------------------------------------------------
// Main scatter-reduce, PERSISTENT grid-stride version.
// Each resident block stages the 2.2KB active-mask in SMEM ONCE, then loops
// over ~12 grid-stride chunks of 4 synapses/thread:
//   2x int4  (four (post,pre) records, coalesced, evict-first)
//   1x float4 (four weights, coalesced, evict-first)
// Inactive synapses contribute exactly 0.0 -> the RED is skipped.
// ---------------------------------------------------------------------------
__global__ __launch_bounds__(256)
void seg_sum_kernel(const int4* __restrict__ idx4,
                    const float4* __restrict__ w4,
                    float* __restrict__ out,
                    int quads, int n_words) {
    __shared__ unsigned int s_mask[MASK_WORDS_MAX];

    // one-time vectorized copy of the mask into SMEM
    {
        const int n_w4 = (n_words + 3) >> 2;
        int4* s4 = reinterpret_cast<int4*>(s_mask);
        const int4* g4 = reinterpret_cast<const int4*>(g_active_mask);
        for (int w = threadIdx.x; w < n_w4; w += blockDim.x) s4[w] = g4[w];
    }
    __syncthreads();

    const int stride = gridDim.x * blockDim.x;
    for (int i = blockIdx.x * blockDim.x + threadIdx.x; i < quads; i += stride) {
        // front-batch the three streaming loads (independent -> MLP 3),
        // evict-first: read-once data should not displace anything in L1.
        int4   a = __ldcs(&idx4[2 * i]);       // (post0, pre0, post1, pre1)
        int4   b = __ldcs(&idx4[2 * i + 1]);   // (post2, pre2, post3, pre3)
        float4 w = __ldcs(&w4[i]);

        const unsigned int m0 = s_mask[((unsigned)a.y) >> 5];
        const unsigned int m1 = s_mask[((unsigned)a.w) >> 5];
        const unsigned int m2 = s_mask[((unsigned)b.y) >> 5];
        const unsigned int m3 = s_mask[((unsigned)b.w) >> 5];

        if ((m0 >> (a.y & 31)) & 1u) atomicAdd(out + a.x, w.x);
        if ((m1 >> (a.w & 31)) & 1u) atomicAdd(out + a.z, w.y);
        if ((m2 >> (b.y & 31)) & 1u) atomicAdd(out + b.x, w.z);
        if ((m3 >> (b.w & 31)) & 1u) atomicAdd(out + b.z, w.w);
    }
}

// Tail for n_syn % 4 (N_SYN = 30M -> empty, but stay general).
__global__ void seg_sum_tail_kernel(const int2* __restrict__ idx2,
                                    const float* __restrict__ wts,
                                    float* __restrict__ out,
                                    int start, int n_syn) {
    int i = start + blockIdx.x * blockDim.x + threadIdx.x;
    if (i >= n_syn) return;
    int2 p = __ldg(&idx2[i]);     // (post, pre)
    unsigned int m = g_active_mask[((unsigned)p.y) >> 5];
    if ((m >> (p.y & 31)) & 1u) atomicAdd(out + p.x, __ldg(&wts[i]));
}

extern "C" void kernel_launch(void* const* d_in, const int* in_sizes, int n_in,
                              void* d_out, int out_size) {
    const int*   inputs_t = (const int*)d_in[0];
    const int*   indices  = (const int*)d_in[1];
    const float* weights  = (const float*)d_in[2];
    float*       out      = (float*)d_out;

    const int n_source = in_sizes[0];
    const int n_syn    = in_sizes[2];
    const int n_post   = out_size;

    // 1) fused prologue: bitmask + output zeroing
    {
        const int n_src32   = (n_source + 31) & ~31;
        const int n_zero_th = (n_post + 3) >> 2;
        const int n_thr     = (n_src32 > n_zero_th) ? n_src32 : n_zero_th;
        prologue_kernel<<<(n_thr + 255) / 256, 256>>>(inputs_t, n_source, out, n_post);
    }

    // 2) persistent scatter-reduce: grid sized to ~16 blocks per SM so each
    //    block stages the mask once and loops (~12 iters at N_SYN=30M).
    const int n_words = (n_source + 31) >> 5;   // 544 for N_SOURCE=17400 (<2048)
    const int quads   = n_syn >> 2;
    if (quads > 0) {
        int blocks = 148 * 16;                  // 2368 persistent-ish blocks
        int needed = (quads + 255) / 256;
        if (needed < blocks) blocks = needed;
        seg_sum_kernel<<<blocks, 256>>>(
            (const int4*)indices, (const float4*)weights, out, quads, n_words);
    }
    const int done = quads << 2;
    if (done < n_syn) {
        seg_sum_tail_kernel<<<1, 256>>>(
            (const int2*)indices, weights, out, done, n_syn);
    }
}

// round 8
// speedup vs baseline: 1.0566x; 1.0566x over previous
#include <cuda_runtime.h>
#include <cuda_bf16.h>

// ---------------------------------------------------------------------------
// LGNInputLayerCell: i_in[post] += weights[s] * (inputs_t[pre[s]] > 0)
// inputs (metadata order):
//   d_in[0] : int32  inputs_t   [N_SOURCE]      (17400)
//   d_in[1] : int32  indices    [N_SYN, 2]      (post, pre) interleaved
//   d_in[2] : float  weights    [N_SYN]
//   d_in[3] : int32  n_post     (unused; out_size == n_post)
// output: float [n_post]
// ---------------------------------------------------------------------------

// Active-source bitmask scratch (global, built by prologue).
// 2048 words = 65536 sources capacity (N_SOURCE = 17400 -> 544 words used).
#define MASK_WORDS_MAX 2048
__device__ unsigned int g_active_mask[MASK_WORDS_MAX];

// ---------------------------------------------------------------------------
// Prologue: build the active bitmask (ballot, 1 thread / source) AND zero the
// 0xAA-poisoned output.
// ---------------------------------------------------------------------------
__global__ void prologue_kernel(const int* __restrict__ inputs_t,
                                int n_source,
                                float* __restrict__ out, int n_post) {
    const int i = blockIdx.x * blockDim.x + threadIdx.x;

    // --- bitmask build: whole warps inside/outside (round-up-32 bound) ---
    const int n_src32 = (n_source + 31) & ~31;
    if (i < n_src32) {
        int v = (i < n_source) ? inputs_t[i] : 0;
        unsigned int b = __ballot_sync(0xffffffffu, v > 0);
        if ((threadIdx.x & 31) == 0) g_active_mask[i >> 5] = b;
    }

    // --- zero output, 4 floats per thread ---
    const int base = i << 2;
    if (base + 3 < n_post) {
        *reinterpret_cast<float4*>(out + base) = make_float4(0.f, 0.f, 0.f, 0.f);
    } else if (base < n_post) {
        for (int j = base; j < n_post; ++j) out[j] = 0.0f;
    }
}

// ---------------------------------------------------------------------------
// Main scatter-reduce: flat grid, EIGHT synapses per thread.
//   4x int4  (eight (post,pre) records, coalesced)  \  6 independent LDG.128
//   2x float4 (eight weights, coalesced)            /  front-batched (MLP 6)
// The deep load batch keeps the DRAM stream in flight while the
// fire-and-forget REDs drain through the LSU/L1tex queue.
// Active mask staged in SMEM; inactive synapses skip the RED entirely.
// ---------------------------------------------------------------------------
__global__ __launch_bounds__(256)
void seg_sum_kernel(const int4* __restrict__ idx4,
                    const float4* __restrict__ w4,
                    float* __restrict__ out,
                    int octs, int n_words) {
    __shared__ unsigned int s_mask[MASK_WORDS_MAX];
    {
        const int n_w4 = (n_words + 3) >> 2;
        int4* s4 = reinterpret_cast<int4*>(s_mask);
        const int4* g4 = reinterpret_cast<const int4*>(g_active_mask);
        for (int w = threadIdx.x; w < n_w4; w += blockDim.x) s4[w] = g4[w];
    }
    __syncthreads();

    const int i = blockIdx.x * blockDim.x + threadIdx.x;
    if (i >= octs) return;

    // 6 independent streaming loads, front-batched.
    int4   a0 = __ldg(&idx4[4 * i + 0]);   // (post0, pre0, post1, pre1)
    int4   a1 = __ldg(&idx4[4 * i + 1]);   // (post2, pre2, post3, pre3)
    int4   a2 = __ldg(&idx4[4 * i + 2]);   // (post4, pre4, post5, pre5)
    int4   a3 = __ldg(&idx4[4 * i + 3]);   // (post6, pre6, post7, pre7)
    float4 w0 = __ldg(&w4[2 * i + 0]);
    float4 w1 = __ldg(&w4[2 * i + 1]);

    const unsigned int m0 = s_mask[((unsigned)a0.y) >> 5];
    const unsigned int m1 = s_mask[((unsigned)a0.w) >> 5];
    const unsigned int m2 = s_mask[((unsigned)a1.y) >> 5];
    const unsigned int m3 = s_mask[((unsigned)a1.w) >> 5];
    const unsigned int m4 = s_mask[((unsigned)a2.y) >> 5];
    const unsigned int m5 = s_mask[((unsigned)a2.w) >> 5];
    const unsigned int m6 = s_mask[((unsigned)a3.y) >> 5];
    const unsigned int m7 = s_mask[((unsigned)a3.w) >> 5];

    if ((m0 >> (a0.y & 31)) & 1u) atomicAdd(out + a0.x, w0.x);
    if ((m1 >> (a0.w & 31)) & 1u) atomicAdd(out + a0.z, w0.y);
    if ((m2 >> (a1.y & 31)) & 1u) atomicAdd(out + a1.x, w0.z);
    if ((m3 >> (a1.w & 31)) & 1u) atomicAdd(out + a1.z, w0.w);
    if ((m4 >> (a2.y & 31)) & 1u) atomicAdd(out + a2.x, w1.x);
    if ((m5 >> (a2.w & 31)) & 1u) atomicAdd(out + a2.z, w1.y);
    if ((m6 >> (a3.y & 31)) & 1u) atomicAdd(out + a3.x, w1.z);
    if ((m7 >> (a3.w & 31)) & 1u) atomicAdd(out + a3.z, w1.w);
}

// Tail for n_syn % 8 (N_SYN = 30M -> exactly divisible, but stay general).
__global__ void seg_sum_tail_kernel(const int2* __restrict__ idx2,
                                    const float* __restrict__ wts,
                                    float* __restrict__ out,
                                    int start, int n_syn) {
    int i = start + blockIdx.x * blockDim.x + threadIdx.x;
    if (i >= n_syn) return;
    int2 p = __ldg(&idx2[i]);     // (post, pre)
    unsigned int m = g_active_mask[((unsigned)p.y) >> 5];
    if ((m >> (p.y & 31)) & 1u) atomicAdd(out + p.x, __ldg(&wts[i]));
}

extern "C" void kernel_launch(void* const* d_in, const int* in_sizes, int n_in,
                              void* d_out, int out_size) {
    const int*   inputs_t = (const int*)d_in[0];
    const int*   indices  = (const int*)d_in[1];
    const float* weights  = (const float*)d_in[2];
    float*       out      = (float*)d_out;

    const int n_source = in_sizes[0];
    const int n_syn    = in_sizes[2];
    const int n_post   = out_size;

    // 1) fused prologue: bitmask + output zeroing
    {
        const int n_src32   = (n_source + 31) & ~31;
        const int n_zero_th = (n_post + 3) >> 2;
        const int n_thr     = (n_src32 > n_zero_th) ? n_src32 : n_zero_th;
        prologue_kernel<<<(n_thr + 255) / 256, 256>>>(inputs_t, n_source, out, n_post);
    }

    // 2) scatter-reduce: flat grid, 8 synapses per thread
    const int n_words = (n_source + 31) >> 5;   // 544 for N_SOURCE=17400 (<2048)
    const int octs    = n_syn >> 3;
    if (octs > 0) {
        seg_sum_kernel<<<(octs + 255) / 256, 256>>>(
            (const int4*)indices, (const float4*)weights, out, octs, n_words);
    }
    const int done = octs << 3;
    if (done < n_syn) {
        seg_sum_tail_kernel<<<1, 256>>>(
            (const int2*)indices, weights, out, done, n_syn);
    }
}